// round 10
// baseline (speedup 1.0000x reference)
#include <cuda_runtime.h>
#include <cuda_fp16.h>

#define NN 50000
#define EE 800000
#define D  128
#define SLOT 64    // max degree per node (Poisson(16): P(>=64) ~ 1e-18)
#define SAH 136    // smem A row stride in halves (conflict-free)

// ---------------- persistent device scratch --------------------------------
__device__ int    g_cnt[NN];
__device__ float  g_dinv[NN];
__device__ int    g_src[(size_t)NN * SLOT];   // bucket CSR (12.8 MB)
__device__ __half g_hh[(size_t)NN * D];       // GEMM output, fp16
__device__ float  g_a[(size_t)NN * D];        // post-aggregation features
__device__ float  g_gsum[D];
__device__ uint4  g_Wf1[4096];
__device__ uint4  g_Wf2[4096];

// ---------------- fp16 split helpers -----------------------------------------
__device__ __forceinline__ void split_f16(float x, __half& hi, __half& lo) {
    hi = __float2half_rn(x);
    lo = __float2half_rn(x - __half2float(hi));
}

__device__ __forceinline__ void mma_f16(float* d, unsigned a0, unsigned a1,
                                        unsigned a2, unsigned a3,
                                        unsigned b0, unsigned b1) {
    asm volatile(
        "mma.sync.aligned.m16n8k16.row.col.f32.f16.f16.f32 "
        "{%0,%1,%2,%3},{%4,%5,%6,%7},{%8,%9},{%0,%1,%2,%3};\n"
        : "+f"(d[0]), "+f"(d[1]), "+f"(d[2]), "+f"(d[3])
        : "r"(a0), "r"(a1), "r"(a2), "r"(a3), "r"(b0), "r"(b1));
}

// ---------------- fused init + weight prep -----------------------------------
__global__ void k_pre(const float* __restrict__ Wa, const float* __restrict__ Wb,
                      uint4* __restrict__ outa, uint4* __restrict__ outb) {
    int b = blockIdx.x;
    if (b < 196) {
        int i = b * 256 + threadIdx.x;
        if (i < NN) g_cnt[i] = 0;
        if (i < D) g_gsum[i] = 0.f;
    } else {
        int gi = (b - 196) * 256 + threadIdx.x;   // 0..8191
        const float* W = (gi < 4096) ? Wa : Wb;
        uint4* out = (gi < 4096) ? outa : outb;
        int i = gi & 4095;
        int lane = i & 31;
        int ntg = (i >> 5) & 15;
        int kc = i >> 9;
        int n = ntg * 8 + (lane >> 2);
        int k0 = kc * 16 + (lane & 3) * 2;
        float w00 = __ldg(&W[k0 * 128 + n]);
        float w01 = __ldg(&W[(k0 + 1) * 128 + n]);
        float w10 = __ldg(&W[(k0 + 8) * 128 + n]);
        float w11 = __ldg(&W[(k0 + 9) * 128 + n]);
        __half h00, l00, h01, l01, h10, l10, h11, l11;
        split_f16(w00, h00, l00);
        split_f16(w01, h01, l01);
        split_f16(w10, h10, l10);
        split_f16(w11, h11, l11);
        __half2 bh0 = __halves2half2(h00, h01);
        __half2 bh1 = __halves2half2(h10, h11);
        __half2 bl0 = __halves2half2(l00, l01);
        __half2 bl1 = __halves2half2(l10, l11);
        out[i] = make_uint4(*(unsigned*)&bh0, *(unsigned*)&bh1,
                            *(unsigned*)&bl0, *(unsigned*)&bl1);
    }
}

// ---------------- bucket scatter ----------------------------------------------
__global__ void k_scatter4(const int4* __restrict__ row4, const int4* __restrict__ col4) {
    int idx = blockIdx.x * blockDim.x + threadIdx.x;
    if (idx < EE / 4) {
        int4 r = __ldg(&row4[idx]);
        int4 c = __ldg(&col4[idx]);
        g_src[(size_t)c.x * SLOT + atomicAdd(&g_cnt[c.x], 1)] = r.x;
        g_src[(size_t)c.y * SLOT + atomicAdd(&g_cnt[c.y], 1)] = r.y;
        g_src[(size_t)c.z * SLOT + atomicAdd(&g_cnt[c.z], 1)] = r.z;
        g_src[(size_t)c.w * SLOT + atomicAdd(&g_cnt[c.w], 1)] = r.w;
    }
}

__global__ void k_dinv() {
    int i = blockIdx.x * 256 + threadIdx.x;
    if (i < NN) g_dinv[i] = rsqrtf((float)(g_cnt[i] + 1));   // +1 self loop
}

// ---------------- tensor-core GEMM (2xFP16: Ah*Bh + Ah*Bl): Hh = X @ W -------
// Tile M=64, N=128 per block (256 thr / 8 warps as 2x4). 32 accs/thread,
// 3 blocks/SM. A fp16 in smem (17.4KB); B hi/lo fragments from global (L1-hot).
__global__ void __launch_bounds__(256, 3) k_gemm_tc(const float* __restrict__ X,
                                                    const uint4* __restrict__ Wf,
                                                    __half* __restrict__ Y) {
    extern __shared__ __half sXh[];   // 64 * SAH halves = 17408 B

    const int t = threadIdx.x;
    const int lane = t & 31;
    const int w = t >> 5;
    const int wm = w >> 2;          // 0..1 (32 rows each)
    const int wn = w & 3;           // 0..3 (32 cols each)
    const int blkRow = blockIdx.x * 64;

    // ---- stage X tile (64 x 128) as fp16 ----
#pragma unroll
    for (int i = 0; i < 8; i++) {
        int idx = t + i * 256;          // 0..2047 float4 slots
        int row = idx >> 5;
        int col = (idx & 31) * 4;
        int gr = blkRow + row;
        float4 v = (gr < NN) ? *(const float4*)(X + (size_t)gr * 128 + col)
                             : make_float4(0.f, 0.f, 0.f, 0.f);
        __half2 h0 = __floats2half2_rn(v.x, v.y);
        __half2 h1 = __floats2half2_rn(v.z, v.w);
        *(__half2*)(sXh + row * SAH + col) = h0;
        *(__half2*)(sXh + row * SAH + col + 2) = h1;
    }
    __syncthreads();

    float acc[2][4][4];
#pragma unroll
    for (int i = 0; i < 2; i++)
#pragma unroll
        for (int j = 0; j < 4; j++)
#pragma unroll
            for (int k = 0; k < 4; k++) acc[i][j][k] = 0.f;

    const int r0 = lane >> 2;
    const int c0 = (lane & 3) * 2;

#pragma unroll
    for (int kc = 0; kc < 8; kc++) {
        const uint4* bf = Wf + ((size_t)kc * 16 + wn * 4) * 32 + lane;
        uint4 bb[4];
#pragma unroll
        for (int nt = 0; nt < 4; nt++) bb[nt] = __ldg(&bf[nt * 32]);

#pragma unroll
        for (int mt = 0; mt < 2; mt++) {
            const int rb = wm * 32 + mt * 16;
            const __half* base = sXh + (rb + r0) * SAH + kc * 16 + c0;
            unsigned a0 = *(const unsigned*)(base);
            unsigned a1 = *(const unsigned*)(base + 8 * SAH);
            unsigned a2 = *(const unsigned*)(base + 8);
            unsigned a3 = *(const unsigned*)(base + 8 * SAH + 8);
#pragma unroll
            for (int nt = 0; nt < 4; nt++) {
                mma_f16(acc[mt][nt], a0, a1, a2, a3, bb[nt].x, bb[nt].y);  // Ah*Bh
                mma_f16(acc[mt][nt], a0, a1, a2, a3, bb[nt].z, bb[nt].w);  // Ah*Bl
            }
        }
    }

#pragma unroll
    for (int mt = 0; mt < 2; mt++) {
#pragma unroll
        for (int nt = 0; nt < 4; nt++) {
            int row = blkRow + wm * 32 + mt * 16 + (lane >> 2);
            int col = wn * 32 + nt * 8 + (lane & 3) * 2;
            if (row < NN) {
                __half2 v = __floats2half2_rn(acc[mt][nt][0], acc[mt][nt][1]);
                *(__half2*)(Y + (size_t)row * 128 + col) = v;
            }
            if (row + 8 < NN) {
                __half2 v = __floats2half2_rn(acc[mt][nt][2], acc[mt][nt][3]);
                *(__half2*)(Y + (size_t)(row + 8) * 128 + col) = v;
            }
        }
    }
}

// ---------------- sparse aggregation (warp per node) -------------------------
template <bool POOL>
__global__ void __launch_bounds__(256) k_agg(const __half* __restrict__ H,
                                             const float* __restrict__ bias,
                                             float* __restrict__ O) {
    __shared__ float sPool[128];
    const int lane = threadIdx.x & 31;
    const int w = threadIdx.x >> 5;
    if (POOL) {
        if (threadIdx.x < 128) sPool[threadIdx.x] = 0.f;
        __syncthreads();
    }
    const int node = blockIdx.x * 8 + w;
    if (node < NN) {
        const int cnt = g_cnt[node];
        const int* sp = g_src + (size_t)node * SLOT;
        const uint2* Hv = (const uint2*)H;
        float4 acc0 = make_float4(0.f, 0.f, 0.f, 0.f);
        float4 acc1 = make_float4(0.f, 0.f, 0.f, 0.f);
        int i = 0;
        for (; i + 1 < cnt; i += 2) {
            int r0 = __ldg(&sp[i]);
            int r1 = __ldg(&sp[i + 1]);
            float d0 = g_dinv[r0], d1 = g_dinv[r1];
            uint2 u0 = __ldg(&Hv[(size_t)r0 * 32 + lane]);
            uint2 u1 = __ldg(&Hv[(size_t)r1 * 32 + lane]);
            float2 a = __half22float2(*(__half2*)&u0.x);
            float2 b = __half22float2(*(__half2*)&u0.y);
            float2 c = __half22float2(*(__half2*)&u1.x);
            float2 d = __half22float2(*(__half2*)&u1.y);
            acc0.x += d0 * a.x; acc0.y += d0 * a.y;
            acc0.z += d0 * b.x; acc0.w += d0 * b.y;
            acc1.x += d1 * c.x; acc1.y += d1 * c.y;
            acc1.z += d1 * d.x; acc1.w += d1 * d.y;
        }
        if (i < cnt) {
            int r0 = __ldg(&sp[i]);
            float d0 = g_dinv[r0];
            uint2 u0 = __ldg(&Hv[(size_t)r0 * 32 + lane]);
            float2 a = __half22float2(*(__half2*)&u0.x);
            float2 b = __half22float2(*(__half2*)&u0.y);
            acc0.x += d0 * a.x; acc0.y += d0 * a.y;
            acc0.z += d0 * b.x; acc0.w += d0 * b.y;
        }
        acc0.x += acc1.x; acc0.y += acc1.y; acc0.z += acc1.z; acc0.w += acc1.w;
        const float dc = g_dinv[node];
        const float dc2 = dc * dc;
        uint2 us = __ldg(&Hv[(size_t)node * 32 + lane]);
        float2 sa = __half22float2(*(__half2*)&us.x);
        float2 sb = __half22float2(*(__half2*)&us.y);
        float4 b4 = ((const float4*)bias)[lane];
        float4 res;
        res.x = fmaxf(dc * acc0.x + dc2 * sa.x + b4.x, 0.f);
        res.y = fmaxf(dc * acc0.y + dc2 * sa.y + b4.y, 0.f);
        res.z = fmaxf(dc * acc0.z + dc2 * sb.x + b4.z, 0.f);
        res.w = fmaxf(dc * acc0.w + dc2 * sb.y + b4.w, 0.f);
        if (!POOL) {
            *(float4*)(O + (size_t)node * 128 + lane * 4) = res;
        } else {
            atomicAdd(&sPool[lane * 4 + 0], res.x);
            atomicAdd(&sPool[lane * 4 + 1], res.y);
            atomicAdd(&sPool[lane * 4 + 2], res.z);
            atomicAdd(&sPool[lane * 4 + 3], res.w);
        }
    }
    if (POOL) {
        __syncthreads();
        if (threadIdx.x < 128) atomicAdd(&g_gsum[threadIdx.x], sPool[threadIdx.x]);
    }
}

// ---------------- classifier head --------------------------------------------
__global__ void k_cls(const float* __restrict__ Wc, const float* __restrict__ bc,
                      float* __restrict__ out) {
    int o = threadIdx.x;
    if (o < 40) {
        float acc = 0.f;
        for (int k = 0; k < 128; k++) acc += g_gsum[k] * Wc[k * 40 + o];
        out[o] = acc * (1.0f / (float)NN) + bc[o];
    }
}

// ---------------- launch ------------------------------------------------------
extern "C" void kernel_launch(void* const* d_in, const int* in_sizes, int n_in,
                              void* d_out, int out_size) {
    const float* x  = (const float*)d_in[0];
    const int*   ei = (const int*)d_in[1];
    const float* W1 = (const float*)d_in[2];
    const float* b1 = (const float*)d_in[3];
    const float* W2 = (const float*)d_in[4];
    const float* b2 = (const float*)d_in[5];
    const float* Wc = (const float*)d_in[6];
    const float* bc = (const float*)d_in[7];
    const int* row = ei;
    const int* col = ei + EE;

    __half* hh_ptr;
    float* a_ptr;
    cudaGetSymbolAddress((void**)&hh_ptr, g_hh);
    cudaGetSymbolAddress((void**)&a_ptr, g_a);
    uint4 *wf1, *wf2;
    cudaGetSymbolAddress((void**)&wf1, g_Wf1);
    cudaGetSymbolAddress((void**)&wf2, g_Wf2);

    const unsigned smem = 64 * SAH * 2;   // 17408 B
    static int smemSet = 0;
    if (!smemSet) {
        cudaFuncSetAttribute(k_gemm_tc, cudaFuncAttributeMaxDynamicSharedMemorySize, smem);
        smemSet = 1;
    }

    k_pre<<<228, 256>>>(W1, W2, wf1, wf2);
    k_scatter4<<<(EE / 4 + 255) / 256, 256>>>((const int4*)row, (const int4*)col);
    k_dinv<<<196, 256>>>();

    k_gemm_tc<<<(NN + 63) / 64, 256, smem>>>(x, wf1, hh_ptr);
    k_agg<false><<<(NN + 7) / 8, 256>>>(hh_ptr, b1, a_ptr);
    k_gemm_tc<<<(NN + 63) / 64, 256, smem>>>(a_ptr, wf2, hh_ptr);
    k_agg<true><<<(NN + 7) / 8, 256>>>(hh_ptr, b2, nullptr);
    k_cls<<<1, 64>>>(Wc, bc, (float*)d_out);
}

// round 11
// speedup vs baseline: 1.0740x; 1.0740x over previous
#include <cuda_runtime.h>
#include <cuda_fp16.h>

#define NN 50000
#define EE 800000
#define D  128
#define SLOT 64    // max degree per node (Poisson(16): P(>=64) ~ 1e-18)
#define SAH 136    // smem A row stride in halves (conflict-free)

// ---------------- persistent device scratch --------------------------------
__device__ int    g_cnt[NN];
__device__ float  g_dinv[NN];
__device__ int    g_src[(size_t)NN * SLOT];   // bucket CSR (12.8 MB)
__device__ __half g_hh[(size_t)NN * D];       // GEMM output, fp16
__device__ __half g_a[(size_t)NN * D];        // post-aggregation feats (fp16)
__device__ float  g_gsum[D];
__device__ uint4  g_Wf1[4096];
__device__ uint4  g_Wf2[4096];

// ---------------- fp16 split helpers -----------------------------------------
__device__ __forceinline__ void split_f16(float x, __half& hi, __half& lo) {
    hi = __float2half_rn(x);
    lo = __float2half_rn(x - __half2float(hi));
}

__device__ __forceinline__ void mma_f16(float* d, unsigned a0, unsigned a1,
                                        unsigned a2, unsigned a3,
                                        unsigned b0, unsigned b1) {
    asm volatile(
        "mma.sync.aligned.m16n8k16.row.col.f32.f16.f16.f32 "
        "{%0,%1,%2,%3},{%4,%5,%6,%7},{%8,%9},{%0,%1,%2,%3};\n"
        : "+f"(d[0]), "+f"(d[1]), "+f"(d[2]), "+f"(d[3])
        : "r"(a0), "r"(a1), "r"(a2), "r"(a3), "r"(b0), "r"(b1));
}

// ---------------- fused init + weight prep -----------------------------------
__global__ void k_pre(const float* __restrict__ Wa, const float* __restrict__ Wb,
                      uint4* __restrict__ outa, uint4* __restrict__ outb) {
    int b = blockIdx.x;
    if (b < 196) {
        int i = b * 256 + threadIdx.x;
        if (i < NN) g_cnt[i] = 0;
        if (i < D) g_gsum[i] = 0.f;
    } else {
        int gi = (b - 196) * 256 + threadIdx.x;   // 0..8191
        const float* W = (gi < 4096) ? Wa : Wb;
        uint4* out = (gi < 4096) ? outa : outb;
        int i = gi & 4095;
        int lane = i & 31;
        int ntg = (i >> 5) & 15;
        int kc = i >> 9;
        int n = ntg * 8 + (lane >> 2);
        int k0 = kc * 16 + (lane & 3) * 2;
        float w00 = __ldg(&W[k0 * 128 + n]);
        float w01 = __ldg(&W[(k0 + 1) * 128 + n]);
        float w10 = __ldg(&W[(k0 + 8) * 128 + n]);
        float w11 = __ldg(&W[(k0 + 9) * 128 + n]);
        __half h00, l00, h01, l01, h10, l10, h11, l11;
        split_f16(w00, h00, l00);
        split_f16(w01, h01, l01);
        split_f16(w10, h10, l10);
        split_f16(w11, h11, l11);
        __half2 bh0 = __halves2half2(h00, h01);
        __half2 bh1 = __halves2half2(h10, h11);
        __half2 bl0 = __halves2half2(l00, l01);
        __half2 bl1 = __halves2half2(l10, l11);
        out[i] = make_uint4(*(unsigned*)&bh0, *(unsigned*)&bh1,
                            *(unsigned*)&bl0, *(unsigned*)&bl1);
    }
}

// ---------------- bucket scatter ----------------------------------------------
__global__ void k_scatter4(const int4* __restrict__ row4, const int4* __restrict__ col4) {
    int idx = blockIdx.x * blockDim.x + threadIdx.x;
    if (idx < EE / 4) {
        int4 r = __ldg(&row4[idx]);
        int4 c = __ldg(&col4[idx]);
        g_src[(size_t)c.x * SLOT + atomicAdd(&g_cnt[c.x], 1)] = r.x;
        g_src[(size_t)c.y * SLOT + atomicAdd(&g_cnt[c.y], 1)] = r.y;
        g_src[(size_t)c.z * SLOT + atomicAdd(&g_cnt[c.z], 1)] = r.z;
        g_src[(size_t)c.w * SLOT + atomicAdd(&g_cnt[c.w], 1)] = r.w;
    }
}

__global__ void k_dinv() {
    int i = blockIdx.x * 256 + threadIdx.x;
    if (i < NN) g_dinv[i] = rsqrtf((float)(g_cnt[i] + 1));   // +1 self loop
}

// ---------------- tensor-core GEMM (2xFP16), software-pipelined --------------
// Tile M=64, N=128 / block (8 warps as 2x4). B fragments double-buffered,
// A fragments hoisted. Input fp32 (x) or fp16 (g_a) via template.
template <typename T>
__global__ void __launch_bounds__(256, 2) k_gemm_tc(const T* __restrict__ X,
                                                    const uint4* __restrict__ Wf,
                                                    __half* __restrict__ Y) {
    extern __shared__ __half sXh[];   // 64 * SAH halves = 17408 B

    const int t = threadIdx.x;
    const int lane = t & 31;
    const int w = t >> 5;
    const int wm = w >> 2;          // 0..1 (32 rows each)
    const int wn = w & 3;           // 0..3 (32 cols each)
    const int blkRow = blockIdx.x * 64;

    // ---- stage X tile (64 x 128) as fp16 ----
    if constexpr (sizeof(T) == 4) {
#pragma unroll
        for (int i = 0; i < 8; i++) {
            int idx = t + i * 256;          // 2048 float4 slots
            int row = idx >> 5;
            int col = (idx & 31) * 4;
            int gr = blkRow + row;
            float4 v = (gr < NN) ? *(const float4*)((const float*)X + (size_t)gr * 128 + col)
                                 : make_float4(0.f, 0.f, 0.f, 0.f);
            __half2 h0 = __floats2half2_rn(v.x, v.y);
            __half2 h1 = __floats2half2_rn(v.z, v.w);
            *(__half2*)(sXh + row * SAH + col) = h0;
            *(__half2*)(sXh + row * SAH + col + 2) = h1;
        }
    } else {
#pragma unroll
        for (int i = 0; i < 4; i++) {
            int idx = t + i * 256;          // 1024 uint4 slots (8 halves each)
            int row = idx >> 4;
            int col = (idx & 15) * 8;
            int gr = blkRow + row;
            uint4 v = (gr < NN) ? *(const uint4*)((const __half*)X + (size_t)gr * 128 + col)
                                : make_uint4(0u, 0u, 0u, 0u);
            *(uint4*)(sXh + row * SAH + col) = v;
        }
    }
    __syncthreads();

    float acc[2][4][4];
#pragma unroll
    for (int i = 0; i < 2; i++)
#pragma unroll
        for (int j = 0; j < 4; j++)
#pragma unroll
            for (int k = 0; k < 4; k++) acc[i][j][k] = 0.f;

    const int r0 = lane >> 2;
    const int c0 = (lane & 3) * 2;
    const uint4* bfw = Wf + (size_t)(wn * 4) * 32 + lane;   // kc stride = 512

    // preload B for kc=0
    uint4 bb[4];
#pragma unroll
    for (int nt = 0; nt < 4; nt++) bb[nt] = __ldg(&bfw[nt * 32]);

#pragma unroll
    for (int kc = 0; kc < 8; kc++) {
        // prefetch next B
        uint4 bbn[4];
        if (kc < 7) {
            const uint4* nf = bfw + (kc + 1) * 512;
#pragma unroll
            for (int nt = 0; nt < 4; nt++) bbn[nt] = __ldg(&nf[nt * 32]);
        }
        // hoist A fragments for both mt
        unsigned a[2][4];
#pragma unroll
        for (int mt = 0; mt < 2; mt++) {
            const __half* base = sXh + (wm * 32 + mt * 16 + r0) * SAH + kc * 16 + c0;
            a[mt][0] = *(const unsigned*)(base);
            a[mt][1] = *(const unsigned*)(base + 8 * SAH);
            a[mt][2] = *(const unsigned*)(base + 8);
            a[mt][3] = *(const unsigned*)(base + 8 * SAH + 8);
        }
#pragma unroll
        for (int mt = 0; mt < 2; mt++) {
#pragma unroll
            for (int nt = 0; nt < 4; nt++) {
                mma_f16(acc[mt][nt], a[mt][0], a[mt][1], a[mt][2], a[mt][3],
                        bb[nt].x, bb[nt].y);   // Ah*Bh
                mma_f16(acc[mt][nt], a[mt][0], a[mt][1], a[mt][2], a[mt][3],
                        bb[nt].z, bb[nt].w);   // Ah*Bl
            }
        }
#pragma unroll
        for (int nt = 0; nt < 4; nt++) bb[nt] = bbn[nt];
    }

#pragma unroll
    for (int mt = 0; mt < 2; mt++) {
#pragma unroll
        for (int nt = 0; nt < 4; nt++) {
            int row = blkRow + wm * 32 + mt * 16 + (lane >> 2);
            int col = wn * 32 + nt * 8 + (lane & 3) * 2;
            if (row < NN) {
                __half2 v = __floats2half2_rn(acc[mt][nt][0], acc[mt][nt][1]);
                *(__half2*)(Y + (size_t)row * 128 + col) = v;
            }
            if (row + 8 < NN) {
                __half2 v = __floats2half2_rn(acc[mt][nt][2], acc[mt][nt][3]);
                *(__half2*)(Y + (size_t)(row + 8) * 128 + col) = v;
            }
        }
    }
}

// ---------------- sparse aggregation (warp per node) -------------------------
// !POOL: store relu(agg+b) as fp16 to O. POOL: reduce into g_gsum.
template <bool POOL>
__global__ void __launch_bounds__(256) k_agg(const __half* __restrict__ H,
                                             const float* __restrict__ bias,
                                             __half* __restrict__ O) {
    __shared__ float sPool[128];
    const int lane = threadIdx.x & 31;
    const int w = threadIdx.x >> 5;
    if (POOL) {
        if (threadIdx.x < 128) sPool[threadIdx.x] = 0.f;
        __syncthreads();
    }
    const int node = blockIdx.x * 8 + w;
    if (node < NN) {
        const int cnt = g_cnt[node];
        const int* sp = g_src + (size_t)node * SLOT;
        const uint2* Hv = (const uint2*)H;
        float4 acc0 = make_float4(0.f, 0.f, 0.f, 0.f);
        float4 acc1 = make_float4(0.f, 0.f, 0.f, 0.f);
        int i = 0;
        for (; i + 1 < cnt; i += 2) {
            int r0 = __ldg(&sp[i]);
            int r1 = __ldg(&sp[i + 1]);
            float d0 = g_dinv[r0], d1 = g_dinv[r1];
            uint2 u0 = __ldg(&Hv[(size_t)r0 * 32 + lane]);
            uint2 u1 = __ldg(&Hv[(size_t)r1 * 32 + lane]);
            float2 a = __half22float2(*(__half2*)&u0.x);
            float2 b = __half22float2(*(__half2*)&u0.y);
            float2 c = __half22float2(*(__half2*)&u1.x);
            float2 d = __half22float2(*(__half2*)&u1.y);
            acc0.x += d0 * a.x; acc0.y += d0 * a.y;
            acc0.z += d0 * b.x; acc0.w += d0 * b.y;
            acc1.x += d1 * c.x; acc1.y += d1 * c.y;
            acc1.z += d1 * d.x; acc1.w += d1 * d.y;
        }
        if (i < cnt) {
            int r0 = __ldg(&sp[i]);
            float d0 = g_dinv[r0];
            uint2 u0 = __ldg(&Hv[(size_t)r0 * 32 + lane]);
            float2 a = __half22float2(*(__half2*)&u0.x);
            float2 b = __half22float2(*(__half2*)&u0.y);
            acc0.x += d0 * a.x; acc0.y += d0 * a.y;
            acc0.z += d0 * b.x; acc0.w += d0 * b.y;
        }
        acc0.x += acc1.x; acc0.y += acc1.y; acc0.z += acc1.z; acc0.w += acc1.w;
        const float dc = g_dinv[node];
        const float dc2 = dc * dc;
        uint2 us = __ldg(&Hv[(size_t)node * 32 + lane]);
        float2 sa = __half22float2(*(__half2*)&us.x);
        float2 sb = __half22float2(*(__half2*)&us.y);
        float4 b4 = ((const float4*)bias)[lane];
        float4 res;
        res.x = fmaxf(dc * acc0.x + dc2 * sa.x + b4.x, 0.f);
        res.y = fmaxf(dc * acc0.y + dc2 * sa.y + b4.y, 0.f);
        res.z = fmaxf(dc * acc0.z + dc2 * sb.x + b4.z, 0.f);
        res.w = fmaxf(dc * acc0.w + dc2 * sb.y + b4.w, 0.f);
        if (!POOL) {
            __half2 h0 = __floats2half2_rn(res.x, res.y);
            __half2 h1 = __floats2half2_rn(res.z, res.w);
            uint2 st = make_uint2(*(unsigned*)&h0, *(unsigned*)&h1);
            *(uint2*)(O + (size_t)node * 128 + lane * 4) = st;
        } else {
            atomicAdd(&sPool[lane * 4 + 0], res.x);
            atomicAdd(&sPool[lane * 4 + 1], res.y);
            atomicAdd(&sPool[lane * 4 + 2], res.z);
            atomicAdd(&sPool[lane * 4 + 3], res.w);
        }
    }
    if (POOL) {
        __syncthreads();
        if (threadIdx.x < 128) atomicAdd(&g_gsum[threadIdx.x], sPool[threadIdx.x]);
    }
}

// ---------------- classifier head --------------------------------------------
__global__ void k_cls(const float* __restrict__ Wc, const float* __restrict__ bc,
                      float* __restrict__ out) {
    int o = threadIdx.x;
    if (o < 40) {
        float acc = 0.f;
        for (int k = 0; k < 128; k++) acc += g_gsum[k] * Wc[k * 40 + o];
        out[o] = acc * (1.0f / (float)NN) + bc[o];
    }
}

// ---------------- launch ------------------------------------------------------
extern "C" void kernel_launch(void* const* d_in, const int* in_sizes, int n_in,
                              void* d_out, int out_size) {
    const float* x  = (const float*)d_in[0];
    const int*   ei = (const int*)d_in[1];
    const float* W1 = (const float*)d_in[2];
    const float* b1 = (const float*)d_in[3];
    const float* W2 = (const float*)d_in[4];
    const float* b2 = (const float*)d_in[5];
    const float* Wc = (const float*)d_in[6];
    const float* bc = (const float*)d_in[7];
    const int* row = ei;
    const int* col = ei + EE;

    __half *hh_ptr, *a_ptr;
    cudaGetSymbolAddress((void**)&hh_ptr, g_hh);
    cudaGetSymbolAddress((void**)&a_ptr, g_a);
    uint4 *wf1, *wf2;
    cudaGetSymbolAddress((void**)&wf1, g_Wf1);
    cudaGetSymbolAddress((void**)&wf2, g_Wf2);

    const unsigned smem = 64 * SAH * 2;   // 17408 B
    static int smemSet = 0;
    if (!smemSet) {
        cudaFuncSetAttribute(k_gemm_tc<float>, cudaFuncAttributeMaxDynamicSharedMemorySize, smem);
        cudaFuncSetAttribute(k_gemm_tc<__half>, cudaFuncAttributeMaxDynamicSharedMemorySize, smem);
        smemSet = 1;
    }

    k_pre<<<228, 256>>>(W1, W2, wf1, wf2);
    k_scatter4<<<(EE / 4 + 255) / 256, 256>>>((const int4*)row, (const int4*)col);
    k_dinv<<<196, 256>>>();

    k_gemm_tc<float><<<(NN + 63) / 64, 256, smem>>>(x, wf1, hh_ptr);
    k_agg<false><<<(NN + 7) / 8, 256>>>(hh_ptr, b1, a_ptr);
    k_gemm_tc<__half><<<(NN + 63) / 64, 256, smem>>>(a_ptr, wf2, hh_ptr);
    k_agg<true><<<(NN + 7) / 8, 256>>>(hh_ptr, b2, nullptr);
    k_cls<<<1, 64>>>(Wc, bc, (float*)d_out);
}

// round 12
// speedup vs baseline: 1.0889x; 1.0139x over previous
#include <cuda_runtime.h>
#include <cuda_fp16.h>

#define NN 50000
#define EE 800000
#define D  128
#define SLOT 64    // max degree per node (Poisson(16): P(>=64) ~ 1e-18)
#define SAH 136    // smem A row stride in halves (conflict-free)

#define GDC_WAIT()   asm volatile("griddepcontrol.wait;" ::: "memory")
#define GDC_LAUNCH() asm volatile("griddepcontrol.launch_dependents;" ::: "memory")

// ---------------- persistent device scratch --------------------------------
__device__ int    g_cnt[NN];
__device__ float  g_dinv[NN];
__device__ int    g_src[(size_t)NN * SLOT];   // bucket CSR (12.8 MB)
__device__ __half g_hh[(size_t)NN * D];       // GEMM output, fp16
__device__ __half g_a[(size_t)NN * D];        // post-aggregation feats (fp16)
__device__ float  g_gsum[D];
__device__ uint4  g_Wf1[4096];
__device__ uint4  g_Wf2[4096];

// ---------------- fp16 split helpers -----------------------------------------
__device__ __forceinline__ void split_f16(float x, __half& hi, __half& lo) {
    hi = __float2half_rn(x);
    lo = __float2half_rn(x - __half2float(hi));
}

__device__ __forceinline__ void mma_f16(float* d, unsigned a0, unsigned a1,
                                        unsigned a2, unsigned a3,
                                        unsigned b0, unsigned b1) {
    asm volatile(
        "mma.sync.aligned.m16n8k16.row.col.f32.f16.f16.f32 "
        "{%0,%1,%2,%3},{%4,%5,%6,%7},{%8,%9},{%0,%1,%2,%3};\n"
        : "+f"(d[0]), "+f"(d[1]), "+f"(d[2]), "+f"(d[3])
        : "r"(a0), "r"(a1), "r"(a2), "r"(a3), "r"(b0), "r"(b1));
}

// ---------------- fused init + weight prep -----------------------------------
__global__ void k_pre(const float* __restrict__ Wa, const float* __restrict__ Wb,
                      uint4* __restrict__ outa, uint4* __restrict__ outb) {
    int b = blockIdx.x;
    if (b < 196) {
        int i = b * 256 + threadIdx.x;
        if (i < NN) g_cnt[i] = 0;
        if (i < D) g_gsum[i] = 0.f;
    } else {
        int gi = (b - 196) * 256 + threadIdx.x;   // 0..8191
        const float* W = (gi < 4096) ? Wa : Wb;
        uint4* out = (gi < 4096) ? outa : outb;
        int i = gi & 4095;
        int lane = i & 31;
        int ntg = (i >> 5) & 15;
        int kc = i >> 9;
        int n = ntg * 8 + (lane >> 2);
        int k0 = kc * 16 + (lane & 3) * 2;
        float w00 = __ldg(&W[k0 * 128 + n]);
        float w01 = __ldg(&W[(k0 + 1) * 128 + n]);
        float w10 = __ldg(&W[(k0 + 8) * 128 + n]);
        float w11 = __ldg(&W[(k0 + 9) * 128 + n]);
        __half h00, l00, h01, l01, h10, l10, h11, l11;
        split_f16(w00, h00, l00);
        split_f16(w01, h01, l01);
        split_f16(w10, h10, l10);
        split_f16(w11, h11, l11);
        __half2 bh0 = __halves2half2(h00, h01);
        __half2 bh1 = __halves2half2(h10, h11);
        __half2 bl0 = __halves2half2(l00, l01);
        __half2 bl1 = __halves2half2(l10, l11);
        out[i] = make_uint4(*(unsigned*)&bh0, *(unsigned*)&bh1,
                            *(unsigned*)&bl0, *(unsigned*)&bl1);
    }
    GDC_LAUNCH();
}

// ---------------- bucket scatter ----------------------------------------------
__global__ void k_scatter4(const int4* __restrict__ row4, const int4* __restrict__ col4) {
    int idx = blockIdx.x * blockDim.x + threadIdx.x;
    if (idx < EE / 4) {
        int4 r = __ldg(&row4[idx]);      // inputs are external: safe pre-wait
        int4 c = __ldg(&col4[idx]);
        GDC_WAIT();                       // g_cnt zeroed by k_pre
        g_src[(size_t)c.x * SLOT + atomicAdd(&g_cnt[c.x], 1)] = r.x;
        g_src[(size_t)c.y * SLOT + atomicAdd(&g_cnt[c.y], 1)] = r.y;
        g_src[(size_t)c.z * SLOT + atomicAdd(&g_cnt[c.z], 1)] = r.z;
        g_src[(size_t)c.w * SLOT + atomicAdd(&g_cnt[c.w], 1)] = r.w;
    } else {
        GDC_WAIT();
    }
    GDC_LAUNCH();
}

__global__ void k_dinv() {
    GDC_WAIT();
    int i = blockIdx.x * 256 + threadIdx.x;
    if (i < NN) g_dinv[i] = rsqrtf((float)(g_cnt[i] + 1));   // +1 self loop
    GDC_LAUNCH();
}

// ---------------- tensor-core GEMM (2xFP16), software-pipelined --------------
template <typename T>
__global__ void __launch_bounds__(256, 2) k_gemm_tc(const T* __restrict__ X,
                                                    const uint4* __restrict__ Wf,
                                                    __half* __restrict__ Y) {
    extern __shared__ __half sXh[];   // 64 * SAH halves = 17408 B

    const int t = threadIdx.x;
    const int lane = t & 31;
    const int w = t >> 5;
    const int wm = w >> 2;          // 0..1 (32 rows each)
    const int wn = w & 3;           // 0..3 (32 cols each)
    const int blkRow = blockIdx.x * 64;

    const int r0 = lane >> 2;
    const int c0 = (lane & 3) * 2;
    const uint4* bfw = Wf + (size_t)(wn * 4) * 32 + lane;   // kc stride = 512

    uint4 bb[4];

    // ---- stage X tile (64 x 128) as fp16 ----
    if constexpr (sizeof(T) == 4) {
        // X is the external input: stage fully BEFORE waiting on upstream.
#pragma unroll
        for (int i = 0; i < 8; i++) {
            int idx = t + i * 256;          // 2048 float4 slots
            int row = idx >> 5;
            int col = (idx & 31) * 4;
            int gr = blkRow + row;
            float4 v = (gr < NN) ? *(const float4*)((const float*)X + (size_t)gr * 128 + col)
                                 : make_float4(0.f, 0.f, 0.f, 0.f);
            __half2 h0 = __floats2half2_rn(v.x, v.y);
            __half2 h1 = __floats2half2_rn(v.z, v.w);
            *(__half2*)(sXh + row * SAH + col) = h0;
            *(__half2*)(sXh + row * SAH + col + 2) = h1;
        }
        GDC_WAIT();   // Wf (from k_pre, transitively complete) read below
#pragma unroll
        for (int nt = 0; nt < 4; nt++) bb[nt] = __ldg(&bfw[nt * 32]);
    } else {
        // Wf is >=2 kernels upstream (transitively complete): preload pre-wait.
#pragma unroll
        for (int nt = 0; nt < 4; nt++) bb[nt] = __ldg(&bfw[nt * 32]);
        GDC_WAIT();   // X = g_a from immediate predecessor agg1
#pragma unroll
        for (int i = 0; i < 4; i++) {
            int idx = t + i * 256;          // 1024 uint4 slots (8 halves each)
            int row = idx >> 4;
            int col = (idx & 15) * 8;
            int gr = blkRow + row;
            uint4 v = (gr < NN) ? *(const uint4*)((const __half*)X + (size_t)gr * 128 + col)
                                : make_uint4(0u, 0u, 0u, 0u);
            *(uint4*)(sXh + row * SAH + col) = v;
        }
    }
    __syncthreads();

    float acc[2][4][4];
#pragma unroll
    for (int i = 0; i < 2; i++)
#pragma unroll
        for (int j = 0; j < 4; j++)
#pragma unroll
            for (int k = 0; k < 4; k++) acc[i][j][k] = 0.f;

#pragma unroll
    for (int kc = 0; kc < 8; kc++) {
        uint4 bbn[4];
        if (kc < 7) {
            const uint4* nf = bfw + (kc + 1) * 512;
#pragma unroll
            for (int nt = 0; nt < 4; nt++) bbn[nt] = __ldg(&nf[nt * 32]);
        }
        unsigned a[2][4];
#pragma unroll
        for (int mt = 0; mt < 2; mt++) {
            const __half* base = sXh + (wm * 32 + mt * 16 + r0) * SAH + kc * 16 + c0;
            a[mt][0] = *(const unsigned*)(base);
            a[mt][1] = *(const unsigned*)(base + 8 * SAH);
            a[mt][2] = *(const unsigned*)(base + 8);
            a[mt][3] = *(const unsigned*)(base + 8 * SAH + 8);
        }
#pragma unroll
        for (int mt = 0; mt < 2; mt++) {
#pragma unroll
            for (int nt = 0; nt < 4; nt++) {
                mma_f16(acc[mt][nt], a[mt][0], a[mt][1], a[mt][2], a[mt][3],
                        bb[nt].x, bb[nt].y);   // Ah*Bh
                mma_f16(acc[mt][nt], a[mt][0], a[mt][1], a[mt][2], a[mt][3],
                        bb[nt].z, bb[nt].w);   // Ah*Bl
            }
        }
#pragma unroll
        for (int nt = 0; nt < 4; nt++) bb[nt] = bbn[nt];
    }

#pragma unroll
    for (int mt = 0; mt < 2; mt++) {
#pragma unroll
        for (int nt = 0; nt < 4; nt++) {
            int row = blkRow + wm * 32 + mt * 16 + (lane >> 2);
            int col = wn * 32 + nt * 8 + (lane & 3) * 2;
            if (row < NN) {
                __half2 v = __floats2half2_rn(acc[mt][nt][0], acc[mt][nt][1]);
                *(__half2*)(Y + (size_t)row * 128 + col) = v;
            }
            if (row + 8 < NN) {
                __half2 v = __floats2half2_rn(acc[mt][nt][2], acc[mt][nt][3]);
                *(__half2*)(Y + (size_t)(row + 8) * 128 + col) = v;
            }
        }
    }
    GDC_LAUNCH();
}

// ---------------- sparse aggregation (warp per node) -------------------------
// !POOL: store relu(agg+b) as fp16 to O. POOL: reduce into g_gsum.
template <bool POOL>
__global__ void __launch_bounds__(256) k_agg(const __half* __restrict__ H,
                                             const float* __restrict__ bias,
                                             __half* __restrict__ O) {
    __shared__ float sPool[128];
    const int lane = threadIdx.x & 31;
    const int w = threadIdx.x >> 5;
    if (POOL) {
        if (threadIdx.x < 128) sPool[threadIdx.x] = 0.f;
        __syncthreads();
    }
    const int node = blockIdx.x * 8 + w;
    if (node < NN) {
        // cnt/src/dinv/bias are >=2 kernels upstream: safe pre-wait.
        const int cnt = g_cnt[node];
        const int* sp = g_src + (size_t)node * SLOT;
        const float dc = g_dinv[node];
        float4 b4 = ((const float4*)bias)[lane];
        int pr0 = (cnt > 0) ? __ldg(&sp[0]) : node;   // prefetch first index
        GDC_WAIT();                                   // H from immediate pred
        const uint2* Hv = (const uint2*)H;
        float4 acc0 = make_float4(0.f, 0.f, 0.f, 0.f);
        float4 acc1 = make_float4(0.f, 0.f, 0.f, 0.f);
        int i = 0;
        for (; i + 1 < cnt; i += 2) {
            int r0 = (i == 0) ? pr0 : __ldg(&sp[i]);
            int r1 = __ldg(&sp[i + 1]);
            float d0 = g_dinv[r0], d1 = g_dinv[r1];
            uint2 u0 = __ldg(&Hv[(size_t)r0 * 32 + lane]);
            uint2 u1 = __ldg(&Hv[(size_t)r1 * 32 + lane]);
            float2 a = __half22float2(*(__half2*)&u0.x);
            float2 b = __half22float2(*(__half2*)&u0.y);
            float2 c = __half22float2(*(__half2*)&u1.x);
            float2 d = __half22float2(*(__half2*)&u1.y);
            acc0.x += d0 * a.x; acc0.y += d0 * a.y;
            acc0.z += d0 * b.x; acc0.w += d0 * b.y;
            acc1.x += d1 * c.x; acc1.y += d1 * c.y;
            acc1.z += d1 * d.x; acc1.w += d1 * d.y;
        }
        if (i < cnt) {
            int r0 = (i == 0) ? pr0 : __ldg(&sp[i]);
            float d0 = g_dinv[r0];
            uint2 u0 = __ldg(&Hv[(size_t)r0 * 32 + lane]);
            float2 a = __half22float2(*(__half2*)&u0.x);
            float2 b = __half22float2(*(__half2*)&u0.y);
            acc0.x += d0 * a.x; acc0.y += d0 * a.y;
            acc0.z += d0 * b.x; acc0.w += d0 * b.y;
        }
        acc0.x += acc1.x; acc0.y += acc1.y; acc0.z += acc1.z; acc0.w += acc1.w;
        const float dc2 = dc * dc;
        uint2 us = __ldg(&Hv[(size_t)node * 32 + lane]);
        float2 sa = __half22float2(*(__half2*)&us.x);
        float2 sb = __half22float2(*(__half2*)&us.y);
        float4 res;
        res.x = fmaxf(dc * acc0.x + dc2 * sa.x + b4.x, 0.f);
        res.y = fmaxf(dc * acc0.y + dc2 * sa.y + b4.y, 0.f);
        res.z = fmaxf(dc * acc0.z + dc2 * sb.x + b4.z, 0.f);
        res.w = fmaxf(dc * acc0.w + dc2 * sb.y + b4.w, 0.f);
        if (!POOL) {
            __half2 h0 = __floats2half2_rn(res.x, res.y);
            __half2 h1 = __floats2half2_rn(res.z, res.w);
            uint2 st = make_uint2(*(unsigned*)&h0, *(unsigned*)&h1);
            *(uint2*)(O + (size_t)node * 128 + lane * 4) = st;
        } else {
            atomicAdd(&sPool[lane * 4 + 0], res.x);
            atomicAdd(&sPool[lane * 4 + 1], res.y);
            atomicAdd(&sPool[lane * 4 + 2], res.z);
            atomicAdd(&sPool[lane * 4 + 3], res.w);
        }
    } else {
        GDC_WAIT();
    }
    if (POOL) {
        __syncthreads();
        if (threadIdx.x < 128) atomicAdd(&g_gsum[threadIdx.x], sPool[threadIdx.x]);
    }
    GDC_LAUNCH();
}

// ---------------- classifier head --------------------------------------------
__global__ void k_cls(const float* __restrict__ Wc, const float* __restrict__ bc,
                      float* __restrict__ out) {
    int o = threadIdx.x;
    float wcol[128 / 4];
    // Wc/bc are external inputs: prefetch nothing heavy; just wait then compute.
    GDC_WAIT();
    if (o < 40) {
        float acc = 0.f;
#pragma unroll 4
        for (int k = 0; k < 128; k++) acc += g_gsum[k] * __ldg(&Wc[k * 40 + o]);
        out[o] = acc * (1.0f / (float)NN) + __ldg(&bc[o]);
    }
    (void)wcol;
}

// ---------------- PDL launch helper -------------------------------------------
template <typename... Args>
static void launch_pdl(void (*kern)(Args...), dim3 grid, dim3 block,
                       size_t smem, Args... args) {
    cudaLaunchConfig_t cfg = {};
    cfg.gridDim = grid;
    cfg.blockDim = block;
    cfg.dynamicSmemBytes = smem;
    cudaLaunchAttribute attr[1];
    attr[0].id = cudaLaunchAttributeProgrammaticStreamSerialization;
    attr[0].val.programmaticStreamSerializationAllowed = 1;
    cfg.attrs = attr;
    cfg.numAttrs = 1;
    cudaLaunchKernelEx(&cfg, kern, args...);
}

// ---------------- launch ------------------------------------------------------
extern "C" void kernel_launch(void* const* d_in, const int* in_sizes, int n_in,
                              void* d_out, int out_size) {
    const float* x  = (const float*)d_in[0];
    const int*   ei = (const int*)d_in[1];
    const float* W1 = (const float*)d_in[2];
    const float* b1 = (const float*)d_in[3];
    const float* W2 = (const float*)d_in[4];
    const float* b2 = (const float*)d_in[5];
    const float* Wc = (const float*)d_in[6];
    const float* bc = (const float*)d_in[7];
    const int4* row4 = (const int4*)ei;
    const int4* col4 = (const int4*)(ei + EE);

    __half *hh_ptr, *a_ptr;
    cudaGetSymbolAddress((void**)&hh_ptr, g_hh);
    cudaGetSymbolAddress((void**)&a_ptr, g_a);
    uint4 *wf1, *wf2;
    cudaGetSymbolAddress((void**)&wf1, g_Wf1);
    cudaGetSymbolAddress((void**)&wf2, g_Wf2);

    const unsigned smem = 64 * SAH * 2;   // 17408 B
    static int smemSet = 0;
    if (!smemSet) {
        cudaFuncSetAttribute(k_gemm_tc<float>, cudaFuncAttributeMaxDynamicSharedMemorySize, smem);
        cudaFuncSetAttribute(k_gemm_tc<__half>, cudaFuncAttributeMaxDynamicSharedMemorySize, smem);
        smemSet = 1;
    }

    k_pre<<<228, 256>>>(W1, W2, wf1, wf2);
    launch_pdl(k_scatter4, dim3((EE / 4 + 255) / 256), dim3(256), 0, row4, col4);
    launch_pdl(k_dinv, dim3(196), dim3(256), (size_t)0);
    launch_pdl(k_gemm_tc<float>, dim3((NN + 63) / 64), dim3(256), (size_t)smem,
               x, (const uint4*)wf1, hh_ptr);
    launch_pdl(k_agg<false>, dim3((NN + 7) / 8), dim3(256), 0,
               (const __half*)hh_ptr, b1, a_ptr);
    launch_pdl(k_gemm_tc<__half>, dim3((NN + 63) / 64), dim3(256), (size_t)smem,
               (const __half*)a_ptr, (const uint4*)wf2, hh_ptr);
    launch_pdl(k_agg<true>, dim3((NN + 7) / 8), dim3(256), 0,
               (const __half*)hh_ptr, b2, (__half*)nullptr);
    launch_pdl(k_cls, dim3(1), dim3(64), 0, Wc, bc, (float*)d_out);
}